// round 2
// baseline (speedup 1.0000x reference)
#include <cuda_runtime.h>

#define MAX_BLOCKS 2048
#define NTHREADS 256
#define GRID_BLOCKS (148 * 8)   // one full wave at occupancy 8

// Per-block partial sums: {iou_sum, valid_cnt}. Written unconditionally by
// every block each launch -> no init kernel, no atomics, deterministic.
__device__ float2 g_part[MAX_BLOCKS];

__device__ __forceinline__ void iou_accum(const float4 p, const float4 t,
                                          float& lsum, float& lcnt) {
    float p_x1 = p.x - p.z * 0.5f;
    float p_x2 = p.x + p.z * 0.5f;
    float p_y1 = p.y - p.w * 0.5f;
    float p_y2 = p.y + p.w * 0.5f;

    float t_x1 = t.x - t.z * 0.5f;
    float t_x2 = t.x + t.z * 0.5f;
    float t_y1 = t.y - t.w * 0.5f;
    float t_y2 = t.y + t.w * 0.5f;

    float ix = fminf(p_x2, t_x2) - fmaxf(p_x1, t_x1);
    float iy = fminf(p_y2, t_y2) - fmaxf(p_y1, t_y1);
    float inter = fmaxf(ix, 0.0f) * fmaxf(iy, 0.0f);

    float area_p = fabsf((p_x2 - p_x1) * (p_y2 - p_y1));
    float area_t = fabsf((t_x2 - t_x1) * (t_y2 - t_y1));

    float iou = inter / (area_p + area_t - inter + 1e-6f);

    bool valid = !(t.x == -1.0f && t.y == -1.0f &&
                   t.z == -1.0f && t.w == -1.0f);
    if (valid) {
        lsum += iou;
        lcnt += 1.0f;
    }
}

__global__ void __launch_bounds__(NTHREADS)
iou_reduce_kernel(const float4* __restrict__ pred,
                  const float4* __restrict__ truth,
                  int n) {
    float lsum = 0.0f;
    float lcnt = 0.0f;

    int tid = blockIdx.x * NTHREADS + threadIdx.x;
    int S = gridDim.x * NTHREADS;

    int i = tid;
    // Unrolled x4: 8 independent 16B loads in flight per iteration.
    for (; i + 3 * S < n; i += 4 * S) {
        float4 p0 = __ldcs(pred + i);
        float4 p1 = __ldcs(pred + i + S);
        float4 p2 = __ldcs(pred + i + 2 * S);
        float4 p3 = __ldcs(pred + i + 3 * S);
        float4 t0 = __ldcs(truth + i);
        float4 t1 = __ldcs(truth + i + S);
        float4 t2 = __ldcs(truth + i + 2 * S);
        float4 t3 = __ldcs(truth + i + 3 * S);
        iou_accum(p0, t0, lsum, lcnt);
        iou_accum(p1, t1, lsum, lcnt);
        iou_accum(p2, t2, lsum, lcnt);
        iou_accum(p3, t3, lsum, lcnt);
    }
    for (; i < n; i += S) {
        float4 p = __ldcs(pred + i);
        float4 t = __ldcs(truth + i);
        iou_accum(p, t, lsum, lcnt);
    }

    // Warp reduce
    #pragma unroll
    for (int off = 16; off > 0; off >>= 1) {
        lsum += __shfl_down_sync(0xffffffffu, lsum, off);
        lcnt += __shfl_down_sync(0xffffffffu, lcnt, off);
    }

    __shared__ float ssum[NTHREADS / 32];
    __shared__ float scnt[NTHREADS / 32];
    int warp = threadIdx.x >> 5;
    int lane = threadIdx.x & 31;
    if (lane == 0) {
        ssum[warp] = lsum;
        scnt[warp] = lcnt;
    }
    __syncthreads();

    if (warp == 0) {
        float bsum = (lane < NTHREADS / 32) ? ssum[lane] : 0.0f;
        float bcnt = (lane < NTHREADS / 32) ? scnt[lane] : 0.0f;
        #pragma unroll
        for (int off = 4; off > 0; off >>= 1) {
            bsum += __shfl_down_sync(0xffffffffu, bsum, off);
            bcnt += __shfl_down_sync(0xffffffffu, bcnt, off);
        }
        if (lane == 0) {
            g_part[blockIdx.x] = make_float2(bsum, bcnt);
        }
    }
}

__global__ void __launch_bounds__(1024)
iou_finalize_kernel(float* __restrict__ out, int out_size, int nblocks) {
    double lsum = 0.0;
    double lcnt = 0.0;
    for (int i = threadIdx.x; i < nblocks; i += 1024) {
        float2 v = g_part[i];
        lsum += (double)v.x;
        lcnt += (double)v.y;
    }
    // Warp reduce (double via two shuffles handled by compiler)
    #pragma unroll
    for (int off = 16; off > 0; off >>= 1) {
        lsum += __shfl_down_sync(0xffffffffu, lsum, off);
        lcnt += __shfl_down_sync(0xffffffffu, lcnt, off);
    }
    __shared__ double ssum[32];
    __shared__ double scnt[32];
    int warp = threadIdx.x >> 5;
    int lane = threadIdx.x & 31;
    if (lane == 0) { ssum[warp] = lsum; scnt[warp] = lcnt; }
    __syncthreads();
    if (warp == 0) {
        double bsum = (lane < 32) ? ssum[lane] : 0.0;
        double bcnt = (lane < 32) ? scnt[lane] : 0.0;
        #pragma unroll
        for (int off = 16; off > 0; off >>= 1) {
            bsum += __shfl_down_sync(0xffffffffu, bsum, off);
            bcnt += __shfl_down_sync(0xffffffffu, bcnt, off);
        }
        if (lane == 0) {
            float m = (bcnt > 0.0)
                        ? (float)(bsum / (bcnt < 1.0 ? 1.0 : bcnt))
                        : 0.0f;
            for (int i = 0; i < out_size; i++) out[i] = m;
        }
    }
}

extern "C" void kernel_launch(void* const* d_in, const int* in_sizes, int n_in,
                              void* d_out, int out_size) {
    const float4* pred  = (const float4*)d_in[0];
    const float4* truth = (const float4*)d_in[1];
    int n = in_sizes[0] / 4;   // number of boxes (float4 elements)

    int blocks = GRID_BLOCKS;
    int needed = (n + NTHREADS - 1) / NTHREADS;
    if (blocks > needed) blocks = needed;
    if (blocks > MAX_BLOCKS) blocks = MAX_BLOCKS;

    iou_reduce_kernel<<<blocks, NTHREADS>>>(pred, truth, n);
    iou_finalize_kernel<<<1, 1024>>>((float*)d_out, out_size, blocks);
}

// round 3
// speedup vs baseline: 1.1162x; 1.1162x over previous
#include <cuda_runtime.h>

#define MAX_BLOCKS 4096
#define NTHREADS 256
#define GRID_BLOCKS (148 * 16)

// Per-block partials {iou_sum, valid_cnt}; overwritten every launch.
__device__ float2 g_part[MAX_BLOCKS];
// Completion counter; atomicInc wraps to 0 after the last block -> self-resetting.
__device__ unsigned int g_count;

__device__ __forceinline__ void iou_accum(const float4 p, const float4 t,
                                          float& lsum, float& lcnt) {
    float p_x1 = p.x - p.z * 0.5f;
    float p_x2 = p.x + p.z * 0.5f;
    float p_y1 = p.y - p.w * 0.5f;
    float p_y2 = p.y + p.w * 0.5f;

    float t_x1 = t.x - t.z * 0.5f;
    float t_x2 = t.x + t.z * 0.5f;
    float t_y1 = t.y - t.w * 0.5f;
    float t_y2 = t.y + t.w * 0.5f;

    float ix = fminf(p_x2, t_x2) - fmaxf(p_x1, t_x1);
    float iy = fminf(p_y2, t_y2) - fmaxf(p_y1, t_y1);
    float inter = fmaxf(ix, 0.0f) * fmaxf(iy, 0.0f);

    float area_p = fabsf((p_x2 - p_x1) * (p_y2 - p_y1));
    float area_t = fabsf((t_x2 - t_x1) * (t_y2 - t_y1));

    float iou = inter / (area_p + area_t - inter + 1e-6f);

    bool valid = !(t.x == -1.0f && t.y == -1.0f &&
                   t.z == -1.0f && t.w == -1.0f);
    if (valid) {
        lsum += iou;
        lcnt += 1.0f;
    }
}

// Block-level reduce of (lsum,lcnt) in fp32; result valid in thread 0.
__device__ __forceinline__ float2 block_reduce(float lsum, float lcnt) {
    #pragma unroll
    for (int off = 16; off > 0; off >>= 1) {
        lsum += __shfl_down_sync(0xffffffffu, lsum, off);
        lcnt += __shfl_down_sync(0xffffffffu, lcnt, off);
    }
    __shared__ float ssum[NTHREADS / 32];
    __shared__ float scnt[NTHREADS / 32];
    int warp = threadIdx.x >> 5;
    int lane = threadIdx.x & 31;
    if (lane == 0) { ssum[warp] = lsum; scnt[warp] = lcnt; }
    __syncthreads();
    float bsum = 0.0f, bcnt = 0.0f;
    if (warp == 0) {
        bsum = (lane < NTHREADS / 32) ? ssum[lane] : 0.0f;
        bcnt = (lane < NTHREADS / 32) ? scnt[lane] : 0.0f;
        #pragma unroll
        for (int off = 4; off > 0; off >>= 1) {
            bsum += __shfl_down_sync(0xffffffffu, bsum, off);
            bcnt += __shfl_down_sync(0xffffffffu, bcnt, off);
        }
    }
    return make_float2(bsum, bcnt);
}

__global__ void __launch_bounds__(NTHREADS)
iou_fused_kernel(const float4* __restrict__ pred,
                 const float4* __restrict__ truth,
                 int n, float* __restrict__ out, int out_size) {
    float lsum = 0.0f;
    float lcnt = 0.0f;

    int tid = blockIdx.x * NTHREADS + threadIdx.x;
    int S = gridDim.x * NTHREADS;

    int i = tid;
    for (; i + S < n; i += 2 * S) {
        float4 p0 = __ldcs(pred + i);
        float4 t0 = __ldcs(truth + i);
        float4 p1 = __ldcs(pred + i + S);
        float4 t1 = __ldcs(truth + i + S);
        iou_accum(p0, t0, lsum, lcnt);
        iou_accum(p1, t1, lsum, lcnt);
    }
    for (; i < n; i += S) {
        float4 p = __ldcs(pred + i);
        float4 t = __ldcs(truth + i);
        iou_accum(p, t, lsum, lcnt);
    }

    float2 bp = block_reduce(lsum, lcnt);
    __shared__ bool is_last;
    if (threadIdx.x == 0) {
        g_part[blockIdx.x] = bp;
        __threadfence();
        unsigned int old = atomicInc(&g_count, gridDim.x - 1);
        is_last = (old == gridDim.x - 1);   // counter wrapped to 0 -> reset done
    }
    __syncthreads();

    if (is_last) {
        // Final reduction over all block partials (L2-resident, ~9.5 KB).
        double dsum = 0.0, dcnt = 0.0;
        for (int b = threadIdx.x; b < gridDim.x; b += NTHREADS) {
            float2 v = g_part[b];
            dsum += (double)v.x;
            dcnt += (double)v.y;
        }
        #pragma unroll
        for (int off = 16; off > 0; off >>= 1) {
            dsum += __shfl_down_sync(0xffffffffu, dsum, off);
            dcnt += __shfl_down_sync(0xffffffffu, dcnt, off);
        }
        __shared__ double dssum[NTHREADS / 32];
        __shared__ double dscnt[NTHREADS / 32];
        int warp = threadIdx.x >> 5;
        int lane = threadIdx.x & 31;
        if (lane == 0) { dssum[warp] = dsum; dscnt[warp] = dcnt; }
        __syncthreads();
        if (warp == 0) {
            double fsum = (lane < NTHREADS / 32) ? dssum[lane] : 0.0;
            double fcnt = (lane < NTHREADS / 32) ? dscnt[lane] : 0.0;
            #pragma unroll
            for (int off = 4; off > 0; off >>= 1) {
                fsum += __shfl_down_sync(0xffffffffu, fsum, off);
                fcnt += __shfl_down_sync(0xffffffffu, fcnt, off);
            }
            if (lane == 0) {
                float m = (fcnt > 0.0)
                            ? (float)(fsum / (fcnt < 1.0 ? 1.0 : fcnt))
                            : 0.0f;
                for (int k = 0; k < out_size; k++) out[k] = m;
            }
        }
    }
}

extern "C" void kernel_launch(void* const* d_in, const int* in_sizes, int n_in,
                              void* d_out, int out_size) {
    const float4* pred  = (const float4*)d_in[0];
    const float4* truth = (const float4*)d_in[1];
    int n = in_sizes[0] / 4;   // number of boxes (float4 elements)

    int blocks = GRID_BLOCKS;
    int needed = (n + NTHREADS - 1) / NTHREADS;
    if (blocks > needed) blocks = needed;
    if (blocks > MAX_BLOCKS) blocks = MAX_BLOCKS;

    iou_fused_kernel<<<blocks, NTHREADS>>>(pred, truth, n,
                                           (float*)d_out, out_size);
}